// round 8
// baseline (speedup 1.0000x reference)
#include <cuda_runtime.h>
#include <cstdint>
#include <cstddef>

#define MAX_N 50000
#define MAX_E 800000
#define TILE_E 256
#define XSTRIDE 260   // floats; 260*4=1040B rows, 16B-aligned, 4-float bank shift

// Scratch (static device globals — no runtime allocation; zero-initialized)
__device__ float g_s[MAX_N * 64];            // per-node s0(16) + s1(16x3)
__device__ float g_agg[MAX_N * 176];         // m0a16|m0b16|m1a48|m1b48|m1c48
__device__ float g_wf[(size_t)MAX_E * 80];   // per-edge MLP out, CSR-permuted rows
__device__ float g_yp[(size_t)MAX_E * 4];    // eattr, CSR-permuted
__device__ int   g_dstp[MAX_E];              // edge dst, CSR-permuted
__device__ int   g_pos[MAX_E];               // edge -> CSR slot
__device__ int   g_deg[MAX_N];               // zeroed at end of each call
__device__ int   g_off[MAX_N + 1];
__device__ int   g_cur[MAX_N];

// ---------- packed fp32x2 helpers (sm_103a) ----------
__device__ __forceinline__ unsigned long long pk2s(float a) {
    unsigned long long r;
    asm("mov.b64 %0, {%1,%1};" : "=l"(r) : "f"(a));
    return r;
}
__device__ __forceinline__ void upk2(unsigned long long v, float& a, float& b) {
    asm("mov.b64 {%0,%1}, %2;" : "=f"(a), "=f"(b) : "l"(v));
}
__device__ __forceinline__ void ff2(unsigned long long& d, unsigned long long a, unsigned long long b) {
    asm("fma.rn.f32x2 %0, %1, %2, %0;" : "+l"(d) : "l"(a), "l"(b));
}
__device__ __forceinline__ float silu(float v) {
    return v / (1.f + __expf(-v));
}

// ======================================================================
// CSR build
// ======================================================================
__global__ void __launch_bounds__(256) hist_kernel(const int* __restrict__ esrc, int E)
{
    int e = blockIdx.x * 256 + threadIdx.x;
    if (e < E) atomicAdd(&g_deg[__ldg(esrc + e)], 1);
}

__global__ void __launch_bounds__(1024) scan_kernel(int N, int E)
{
    __shared__ int part[1024];
    int t = threadIdx.x;
    const int chunk = (MAX_N + 1023) / 1024;   // 49
    int start = t * chunk;
    int end = start + chunk; if (end > N) end = N;
    int s = 0;
    if (start < N) for (int i = start; i < end; i++) s += g_deg[i];
    part[t] = s;
    __syncthreads();
    for (int off = 1; off < 1024; off <<= 1) {
        int v = (t >= off) ? part[t - off] : 0;
        __syncthreads();
        part[t] += v;
        __syncthreads();
    }
    int run = part[t] - s;
    if (start < N) {
        for (int i = start; i < end; i++) {
            g_off[i] = run;
            g_cur[i] = run;
            run += g_deg[i];
        }
    }
    if (t == 0) g_off[N] = E;
}

__global__ void __launch_bounds__(256) scatter_kernel(
    const int* __restrict__ esrc, const int* __restrict__ edst,
    const float* __restrict__ eattr, int E)
{
    int e = blockIdx.x * 256 + threadIdx.x;
    if (e >= E) return;
    int s = __ldg(esrc + e);
    int p = atomicAdd(&g_cur[s], 1);
    g_pos[e] = p;
    g_dstp[p] = __ldg(edst + e);
    float4 y = __ldg((const float4*)eattr + e);
    *((float4*)g_yp + p) = y;
}

// ======================================================================
// Fused edge MLP: 256-edge tile, 256 threads, 4 edges/thread.
//   phase1: both output groups (p, p+4) in ONE k-loop: per k =
//           1 act LDS.128 + 4 broadcast weight LDS.128 + 32 ff2 (FMA-bound).
//           h kept in regs; written over X only AFTER a barrier (race-free).
//   phase2: groups gp = p, p+4 (+8 for p<2); 16 ff2 per k per group.
// ======================================================================
__global__ void __launch_bounds__(256) fused_mlp_kernel(
    const float* __restrict__ dist,
    const float* __restrict__ W1, const float* __restrict__ W2, int E)
{
    extern __shared__ float sm[];
    float* sX  = sm;                       // 64 * 260
    float* sW1 = sm + 64 * XSTRIDE;        // 4096
    float* sW2 = sW1 + 4096;               // 5120
    int t = threadIdx.x;

    // load weights, pre-scaled by 1/8
    for (int i = t; i < 1024; i += 256) {
        float4 v = __ldg((const float4*)W1 + i);
        ((float4*)sW1)[i] = make_float4(v.x*0.125f, v.y*0.125f, v.z*0.125f, v.w*0.125f);
    }
    for (int i = t; i < 1280; i += 256) {
        float4 v = __ldg((const float4*)W2 + i);
        ((float4*)sW2)[i] = make_float4(v.x*0.125f, v.y*0.125f, v.z*0.125f, v.w*0.125f);
    }

    int e0 = blockIdx.x * TILE_E;

    // stage: coalesced load of dist rows -> transposed smem X[k][e]
    for (int i = t; i < TILE_E * 16; i += 256) {
        int e = i >> 4, seg = i & 15;
        float4 v = make_float4(0.f, 0.f, 0.f, 0.f);
        if (e0 + e < E)
            v = __ldg((const float4*)(dist + (size_t)(e0 + e) * 64) + seg);
        sX[(seg*4 + 0) * XSTRIDE + e] = v.x;
        sX[(seg*4 + 1) * XSTRIDE + e] = v.y;
        sX[(seg*4 + 2) * XSTRIDE + e] = v.z;
        sX[(seg*4 + 3) * XSTRIDE + e] = v.w;
    }
    __syncthreads();

    int q = t & 63, p = t >> 6;   // p in 0..3
    int col = 4 * q;              // this thread's 4 private columns

    // ---------------- phase 1: h = silu(x @ W1/8) ----------------
    // acc[4*e + m]: outputs (8g + 2m, 8g+2m+1) for edge col+e; groups gA=p, gB=p+4
    unsigned long long accA[16], accB[16];
#pragma unroll
    for (int i = 0; i < 16; i++) { accA[i] = 0ULL; accB[i] = 0ULL; }
    {
        const float* xcol = sX + col;
        const float* wA = sW1 + 8 * p;
        const float* wB = sW1 + 8 * (p + 4);
#pragma unroll 4
        for (int k = 0; k < 64; k++) {
            float4 xv = *(const float4*)(xcol + k * XSTRIDE);
            unsigned long long x0 = pk2s(xv.x), x1 = pk2s(xv.y);
            unsigned long long x2 = pk2s(xv.z), x3 = pk2s(xv.w);
            const ulonglong2* ra = (const ulonglong2*)(wA + k * 64);
            ulonglong2 wa0 = ra[0], wa1 = ra[1];
            ff2(accA[0],  x0, wa0.x); ff2(accA[1],  x0, wa0.y); ff2(accA[2],  x0, wa1.x); ff2(accA[3],  x0, wa1.y);
            ff2(accA[4],  x1, wa0.x); ff2(accA[5],  x1, wa0.y); ff2(accA[6],  x1, wa1.x); ff2(accA[7],  x1, wa1.y);
            ff2(accA[8],  x2, wa0.x); ff2(accA[9],  x2, wa0.y); ff2(accA[10], x2, wa1.x); ff2(accA[11], x2, wa1.y);
            ff2(accA[12], x3, wa0.x); ff2(accA[13], x3, wa0.y); ff2(accA[14], x3, wa1.x); ff2(accA[15], x3, wa1.y);
            const ulonglong2* rb = (const ulonglong2*)(wB + k * 64);
            ulonglong2 wb0 = rb[0], wb1 = rb[1];
            ff2(accB[0],  x0, wb0.x); ff2(accB[1],  x0, wb0.y); ff2(accB[2],  x0, wb1.x); ff2(accB[3],  x0, wb1.y);
            ff2(accB[4],  x1, wb0.x); ff2(accB[5],  x1, wb0.y); ff2(accB[6],  x1, wb1.x); ff2(accB[7],  x1, wb1.y);
            ff2(accB[8],  x2, wb0.x); ff2(accB[9],  x2, wb0.y); ff2(accB[10], x2, wb1.x); ff2(accB[11], x2, wb1.y);
            ff2(accB[12], x3, wb0.x); ff2(accB[13], x3, wb0.y); ff2(accB[14], x3, wb1.x); ff2(accB[15], x3, wb1.y);
        }
    }
    __syncthreads();   // ALL X reads complete before h overwrites the tile

    // write h (silu applied) over X rows: group A -> rows 8p.., group B -> rows 8(p+4)..
#pragma unroll
    for (int m = 0; m < 4; m++) {
        float a0,b0,a1,b1,a2,b2,a3,b3;
        upk2(accA[m],      a0, b0); upk2(accA[4 + m],  a1, b1);
        upk2(accA[8 + m],  a2, b2); upk2(accA[12 + m], a3, b3);
        *(float4*)(sX + (8*p + 2*m)     * XSTRIDE + col) = make_float4(silu(a0), silu(a1), silu(a2), silu(a3));
        *(float4*)(sX + (8*p + 2*m + 1) * XSTRIDE + col) = make_float4(silu(b0), silu(b1), silu(b2), silu(b3));
        upk2(accB[m],      a0, b0); upk2(accB[4 + m],  a1, b1);
        upk2(accB[8 + m],  a2, b2); upk2(accB[12 + m], a3, b3);
        *(float4*)(sX + (8*(p+4) + 2*m)     * XSTRIDE + col) = make_float4(silu(a0), silu(a1), silu(a2), silu(a3));
        *(float4*)(sX + (8*(p+4) + 2*m + 1) * XSTRIDE + col) = make_float4(silu(b0), silu(b1), silu(b2), silu(b3));
    }
    __syncthreads();

    // ---------------- phase 2: wf = h @ W2/8 -> g_wf at CSR slot ----------------
    int ebase = e0 + col;
    int pos[4];
    if (ebase + 3 < E) {
        int4 pv = *(const int4*)(g_pos + ebase);
        pos[0] = pv.x; pos[1] = pv.y; pos[2] = pv.z; pos[3] = pv.w;
    } else {
#pragma unroll
        for (int j = 0; j < 4; j++)
            pos[j] = (ebase + j < E) ? g_pos[ebase + j] : 0;
    }

    for (int gp = p; gp < 10; gp += 4) {
        unsigned long long acc[16];
#pragma unroll
        for (int i = 0; i < 16; i++) acc[i] = 0ULL;
        const float* hcol = sX + col;
        const float* wbase = sW2 + 8 * gp;
#pragma unroll 4
        for (int k = 0; k < 64; k++) {
            float4 hv = *(const float4*)(hcol + k * XSTRIDE);
            unsigned long long x0 = pk2s(hv.x), x1 = pk2s(hv.y);
            unsigned long long x2 = pk2s(hv.z), x3 = pk2s(hv.w);
            const ulonglong2* wr = (const ulonglong2*)(wbase + k * 80);
            ulonglong2 w0 = wr[0], w1 = wr[1];
            ff2(acc[0],  x0, w0.x); ff2(acc[1],  x0, w0.y); ff2(acc[2],  x0, w1.x); ff2(acc[3],  x0, w1.y);
            ff2(acc[4],  x1, w0.x); ff2(acc[5],  x1, w0.y); ff2(acc[6],  x1, w1.x); ff2(acc[7],  x1, w1.y);
            ff2(acc[8],  x2, w0.x); ff2(acc[9],  x2, w0.y); ff2(acc[10], x2, w1.x); ff2(acc[11], x2, w1.y);
            ff2(acc[12], x3, w0.x); ff2(acc[13], x3, w0.y); ff2(acc[14], x3, w1.x); ff2(acc[15], x3, w1.y);
        }
#pragma unroll
        for (int j = 0; j < 4; j++) {
            if (ebase + j < E) {
                ulonglong2* wp = (ulonglong2*)(g_wf + (size_t)pos[j] * 80 + 8 * gp);
                ulonglong2 s0; s0.x = acc[4*j];     s0.y = acc[4*j + 1];
                ulonglong2 s1; s1.x = acc[4*j + 2]; s1.y = acc[4*j + 3];
                wp[0] = s0; wp[1] = s1;
            }
        }
    }
}

// ======================================================================
// Kernel: self-interaction s = FCTP(x, attr; W_si)
// ======================================================================
__global__ void __launch_bounds__(128) node_pre_kernel(
    const float* __restrict__ xin, const float* __restrict__ attr,
    const float* __restrict__ Wsi0, const float* __restrict__ Wsi1, int N)
{
    __shared__ float w0[256], w1[256];
    int t = threadIdx.x;
    if (t < 128) { w0[t] = Wsi0[t]; w0[t + 128] = Wsi0[t + 128];
                   w1[t] = Wsi1[t]; w1[t + 128] = Wsi1[t + 128]; }
    __syncthreads();
    int n = blockIdx.x * 128 + t;
    if (n >= N) return;

    float x[64];
    const float4* xp = (const float4*)(xin + (size_t)n * 64);
#pragma unroll
    for (int qq = 0; qq < 16; qq++) {
        float4 v = __ldg(xp + qq);
        x[4*qq] = v.x; x[4*qq+1] = v.y; x[4*qq+2] = v.z; x[4*qq+3] = v.w;
    }
    float a = __ldg(attr + n) * 0.25f;  // attr / sqrt(16)

    float out[64];
#pragma unroll
    for (int u = 0; u < 16; u++) {
        float acc = 0.f;
#pragma unroll
        for (int v = 0; v < 16; v++) acc += x[v] * w0[u*16 + v];
        out[u] = acc * a;
    }
#pragma unroll
    for (int u = 0; u < 16; u++) {
        float a0 = 0.f, a1 = 0.f, a2 = 0.f;
#pragma unroll
        for (int v = 0; v < 16; v++) {
            float wv = w1[u*16 + v];
            a0 += x[16 + 3*v + 0] * wv;
            a1 += x[16 + 3*v + 1] * wv;
            a2 += x[16 + 3*v + 2] * wv;
        }
        out[16 + 3*u + 0] = a0 * a;
        out[16 + 3*u + 1] = a1 * a;
        out[16 + 3*u + 2] = a2 * a;
    }
    float4* sp = (float4*)(g_s + (size_t)n * 64);
#pragma unroll
    for (int qq = 0; qq < 16; qq++)
        sp[qq] = make_float4(out[4*qq], out[4*qq+1], out[4*qq+2], out[4*qq+3]);
}

// ======================================================================
// Aggregation: half-warp (16 lanes) per node, fully sequential CSR walk
// ======================================================================
__global__ void __launch_bounds__(256) agg_kernel(int N)
{
    int u = threadIdx.x & 15;
    int node = blockIdx.x * 16 + (threadIdx.x >> 4);

    int beg = 0, end = 0;
    if (node < N) { beg = __ldg(&g_off[node]); end = __ldg(&g_off[node + 1]); }

    const float is3 = 0.57735026918962576f;   // 1/sqrt(3)
    const float is2 = 0.70710678118654752f;   // 1/sqrt(2)

    float m0a = 0.f, m0b = 0.f;
    float A0 = 0.f, A1 = 0.f, A2 = 0.f;
    float B0 = 0.f, B1 = 0.f, B2 = 0.f;
    float C0 = 0.f, C1 = 0.f, C2 = 0.f;

#pragma unroll 2
    for (int p = beg; p < end; p++) {
        const float* wfp = g_wf + (size_t)p * 80;
        float w0 = __ldg(wfp + u);
        float w1 = __ldg(wfp + 16 + u);
        float w2 = __ldg(wfp + 32 + u);
        float w3 = __ldg(wfp + 48 + u);
        float w4 = __ldg(wfp + 64 + u) * is2;
        int dst = __ldg(g_dstp + p);
        float4 y = __ldg((const float4*)g_yp + p);
        const float* gs = g_s + (size_t)dst * 64;
        float g0 = __ldg(gs + u);
        float ga = __ldg(gs + 16 + 3*u);
        float gb = __ldg(gs + 17 + 3*u);
        float gc = __ldg(gs + 18 + 3*u);

        m0a += w0 * g0 * y.x;
        m0b += w3 * (ga*y.y + gb*y.z + gc*y.w) * is3;
        float w1g = w1 * g0;
        A0 += w1g * y.y;  A1 += w1g * y.z;  A2 += w1g * y.w;
        float w2y = w2 * y.x;
        B0 += w2y * ga;   B1 += w2y * gb;   B2 += w2y * gc;
        C0 += w4 * (gb * y.w - gc * y.z);
        C1 += w4 * (gc * y.y - ga * y.w);
        C2 += w4 * (ga * y.z - gb * y.y);
    }

    if (node < N) {
        float* ab = g_agg + (size_t)node * 176;
        ab[u]         = m0a;
        ab[16 + u]    = m0b;
        ab[32 + 3*u]  = A0;  ab[33 + 3*u]  = A1;  ab[34 + 3*u]  = A2;
        ab[80 + 3*u]  = B0;  ab[81 + 3*u]  = B1;  ab[82 + 3*u]  = B2;
        ab[128 + 3*u] = C0;  ab[129 + 3*u] = C1;  ab[130 + 3*u] = C2;
    }
}

// ======================================================================
// Kernel: per-node output + re-zero g_deg for the next graph replay
// ======================================================================
__global__ void __launch_bounds__(128) node_post_kernel(
    const float* __restrict__ xin, const float* __restrict__ attr,
    const float* __restrict__ Wsc0, const float* __restrict__ Wsc1,
    const float* __restrict__ Wlo0, const float* __restrict__ Wlo1,
    const float* __restrict__ Wal, float* __restrict__ out, int N)
{
    __shared__ float sc0[256], sc1[256], lo0[512], lo1[768], al[32];
    int t = threadIdx.x;
    for (int i = t; i < 256; i += 128) { sc0[i] = Wsc0[i]; sc1[i] = Wsc1[i]; }
    for (int i = t; i < 512; i += 128) lo0[i] = Wlo0[i];
    for (int i = t; i < 768; i += 128) lo1[i] = Wlo1[i];
    if (t < 32) al[t] = Wal[t];
    __syncthreads();

    int n = blockIdx.x * 128 + t;
    if (n >= N) return;

    g_deg[n] = 0;   // invariant for next replay

    const float* ag = g_agg + (size_t)n * 176;
    float o0[16], o1[48];
#pragma unroll
    for (int u = 0; u < 16; u++) o0[u] = 0.f;
#pragma unroll
    for (int j = 0; j < 48; j++) o1[j] = 0.f;
    float alpha = 0.f;

#pragma unroll
    for (int vg = 0; vg < 16; vg += 4) {
        float4 P = __ldg((const float4*)(ag + vg));
        float4 Q = __ldg((const float4*)(ag + 16 + vg));
        const float4* Ap = (const float4*)(ag + 32  + 3*vg);
        const float4* Bp = (const float4*)(ag + 80  + 3*vg);
        const float4* Cp = (const float4*)(ag + 128 + 3*vg);
        float4 Af0 = __ldg(Ap), Af1 = __ldg(Ap+1), Af2 = __ldg(Ap+2);
        float4 Bf0 = __ldg(Bp), Bf1 = __ldg(Bp+1), Bf2 = __ldg(Bp+2);
        float4 Cf0 = __ldg(Cp), Cf1 = __ldg(Cp+1), Cf2 = __ldg(Cp+2);
        float m0aq[4] = {P.x, P.y, P.z, P.w};
        float m0bq[4] = {Q.x, Q.y, Q.z, Q.w};
        float Aq[12] = {Af0.x,Af0.y,Af0.z,Af0.w,Af1.x,Af1.y,Af1.z,Af1.w,Af2.x,Af2.y,Af2.z,Af2.w};
        float Bq[12] = {Bf0.x,Bf0.y,Bf0.z,Bf0.w,Bf1.x,Bf1.y,Bf1.z,Bf1.w,Bf2.x,Bf2.y,Bf2.z,Bf2.w};
        float Cq[12] = {Cf0.x,Cf0.y,Cf0.z,Cf0.w,Cf1.x,Cf1.y,Cf1.z,Cf1.w,Cf2.x,Cf2.y,Cf2.z,Cf2.w};
#pragma unroll
        for (int j = 0; j < 4; j++) {
            int v = vg + j;
            float m0a = m0aq[j] * 0.25f;   // / sqrt(NUM_NEIGHBORS)
            float m0b = m0bq[j] * 0.25f;
            float Ax = Aq[3*j]*0.25f, Ay = Aq[3*j+1]*0.25f, Az = Aq[3*j+2]*0.25f;
            float Bx = Bq[3*j]*0.25f, By = Bq[3*j+1]*0.25f, Bz = Bq[3*j+2]*0.25f;
            float Cx = Cq[3*j]*0.25f, Cy = Cq[3*j+1]*0.25f, Cz = Cq[3*j+2]*0.25f;
            alpha += m0a * al[v] + m0b * al[16 + v];
#pragma unroll
            for (int u = 0; u < 16; u++) {
                o0[u] += m0a * lo0[u*32 + v] + m0b * lo0[u*32 + 16 + v];
                float wa = lo1[u*48 + v], wb = lo1[u*48 + 16 + v], wc = lo1[u*48 + 32 + v];
                o1[u*3 + 0] += Ax * wa + Bx * wb + Cx * wc;
                o1[u*3 + 1] += Ay * wa + By * wb + Cy * wc;
                o1[u*3 + 2] += Az * wa + Bz * wb + Cz * wc;
            }
        }
    }

    float x[64];
    const float4* xp = (const float4*)(xin + (size_t)n * 64);
#pragma unroll
    for (int qq = 0; qq < 16; qq++) {
        float4 v4 = __ldg(xp + qq);
        x[4*qq] = v4.x; x[4*qq+1] = v4.y; x[4*qq+2] = v4.z; x[4*qq+3] = v4.w;
    }
    float a   = __ldg(attr + n);
    float a4  = a * 0.25f;
    float s32 = a * 0.17677669529663689f;
    float s48 = a * 0.14433756729740643f;
    float alphaf = alpha * s32;

    float res[64];
#pragma unroll
    for (int u = 0; u < 16; u++) {
        float sk = 0.f;
#pragma unroll
        for (int v = 0; v < 16; v++) sk += x[v] * sc0[u*16 + v];
        res[u] = o0[u] * s32 * alphaf + sk * a4;
    }
#pragma unroll
    for (int u = 0; u < 16; u++) {
        float sa = 0.f, sb = 0.f, sc = 0.f;
#pragma unroll
        for (int v = 0; v < 16; v++) {
            float wv = sc1[u*16 + v];
            sa += x[16 + 3*v + 0] * wv;
            sb += x[16 + 3*v + 1] * wv;
            sc += x[16 + 3*v + 2] * wv;
        }
        res[16 + 3*u + 0] = o1[3*u + 0] * s48 * alphaf + sa * a4;
        res[16 + 3*u + 1] = o1[3*u + 1] * s48 * alphaf + sb * a4;
        res[16 + 3*u + 2] = o1[3*u + 2] * s48 * alphaf + sc * a4;
    }
    float4* op = (float4*)(out + (size_t)n * 64);
#pragma unroll
    for (int qq = 0; qq < 16; qq++)
        op[qq] = make_float4(res[4*qq], res[4*qq+1], res[4*qq+2], res[4*qq+3]);
}

// ======================================================================
extern "C" void kernel_launch(void* const* d_in, const int* in_sizes, int n_in,
                              void* d_out, int out_size)
{
    const float* node_input = (const float*)d_in[0];
    const float* node_attr  = (const float*)d_in[1];
    const int*   esrc       = (const int*)d_in[2];
    const int*   edst       = (const int*)d_in[3];
    const float* eattr      = (const float*)d_in[4];
    const float* dist       = (const float*)d_in[5];
    const float* Wsi0 = (const float*)d_in[6];
    const float* Wsi1 = (const float*)d_in[7];
    const float* Wsc0 = (const float*)d_in[8];
    const float* Wsc1 = (const float*)d_in[9];
    const float* Wm1  = (const float*)d_in[10];
    const float* Wm2  = (const float*)d_in[11];
    const float* Wlo0 = (const float*)d_in[12];
    const float* Wlo1 = (const float*)d_in[13];
    const float* Wal  = (const float*)d_in[14];

    int N = in_sizes[0] / 64;
    int E = in_sizes[2];

    int smem_bytes = (64 * XSTRIDE + 4096 + 5120) * (int)sizeof(float);  // 103424
    cudaFuncSetAttribute(fused_mlp_kernel, cudaFuncAttributeMaxDynamicSharedMemorySize, smem_bytes);

    hist_kernel<<<(E + 255) / 256, 256>>>(esrc, E);                                   // 0
    scan_kernel<<<1, 1024>>>(N, E);                                                   // 1
    scatter_kernel<<<(E + 255) / 256, 256>>>(esrc, edst, eattr, E);                   // 2
    fused_mlp_kernel<<<(E + TILE_E - 1) / TILE_E, 256, smem_bytes>>>(dist, Wm1, Wm2, E); // 3 (profiled)
    node_pre_kernel<<<(N + 127) / 128, 128>>>(node_input, node_attr, Wsi0, Wsi1, N);  // 4
    agg_kernel<<<(N + 15) / 16, 256>>>(N);                                            // 5
    node_post_kernel<<<(N + 127) / 128, 128>>>(node_input, node_attr, Wsc0, Wsc1,
                                               Wlo0, Wlo1, Wal, (float*)d_out, N);    // 6
}

// round 9
// speedup vs baseline: 1.2416x; 1.2416x over previous
#include <cuda_runtime.h>
#include <cstdint>
#include <cstddef>

#define MAX_N 50000
#define MAX_E 800000
#define TILE_E 128

// Scratch (static device globals — no runtime allocation; zero-initialized)
__device__ float g_s[MAX_N * 64];            // per-node s0(16) + s1(16x3)
__device__ float g_agg[MAX_N * 176];         // m0a16|m0b16|m1a48|m1b48|m1c48
__device__ float g_wf[(size_t)MAX_E * 80];   // per-edge MLP out, CSR-permuted rows
__device__ float g_yp[(size_t)MAX_E * 4];    // eattr, CSR-permuted
__device__ int   g_dstp[MAX_E];              // edge dst, CSR-permuted
__device__ int   g_pos[MAX_E];               // edge -> CSR slot
__device__ int   g_deg[MAX_N];               // zeroed at end of each call
__device__ int   g_off[MAX_N + 1];
__device__ int   g_cur[MAX_N];

__device__ __forceinline__ float silu(float v) {
    return v / (1.f + __expf(-v));
}
// round f32 -> tf32 (rna), result held in an f32 register
__device__ __forceinline__ float tf32r(float x) {
    unsigned u;
    asm("cvt.rna.tf32.f32 %0, %1;" : "=r"(u) : "f"(x));
    return __uint_as_float(u);
}
// m16n8k8 tf32 MMA, accumulate in place
__device__ __forceinline__ void mma_tf32(
    float& d0, float& d1, float& d2, float& d3,
    float a0, float a1, float a2, float a3, float b0, float b1)
{
    asm volatile(
        "mma.sync.aligned.m16n8k8.row.col.f32.tf32.tf32.f32 "
        "{%0,%1,%2,%3}, {%4,%5,%6,%7}, {%8,%9}, {%0,%1,%2,%3};"
        : "+f"(d0), "+f"(d1), "+f"(d2), "+f"(d3)
        : "r"(__float_as_uint(a0)), "r"(__float_as_uint(a1)),
          "r"(__float_as_uint(a2)), "r"(__float_as_uint(a3)),
          "r"(__float_as_uint(b0)), "r"(__float_as_uint(b1)));
}

// ======================================================================
// CSR build
// ======================================================================
__global__ void __launch_bounds__(256) hist_kernel(const int* __restrict__ esrc, int E)
{
    int e = blockIdx.x * 256 + threadIdx.x;
    if (e < E) atomicAdd(&g_deg[__ldg(esrc + e)], 1);
}

__global__ void __launch_bounds__(1024) scan_kernel(int N, int E)
{
    __shared__ int part[1024];
    int t = threadIdx.x;
    const int chunk = (MAX_N + 1023) / 1024;   // 49
    int start = t * chunk;
    int end = start + chunk; if (end > N) end = N;
    int s = 0;
    if (start < N) for (int i = start; i < end; i++) s += g_deg[i];
    part[t] = s;
    __syncthreads();
    for (int off = 1; off < 1024; off <<= 1) {
        int v = (t >= off) ? part[t - off] : 0;
        __syncthreads();
        part[t] += v;
        __syncthreads();
    }
    int run = part[t] - s;
    if (start < N) {
        for (int i = start; i < end; i++) {
            g_off[i] = run;
            g_cur[i] = run;
            run += g_deg[i];
        }
    }
    if (t == 0) g_off[N] = E;
}

__global__ void __launch_bounds__(256) scatter_kernel(
    const int* __restrict__ esrc, const int* __restrict__ edst,
    const float* __restrict__ eattr, int E)
{
    int e = blockIdx.x * 256 + threadIdx.x;
    if (e >= E) return;
    int s = __ldg(esrc + e);
    int p = atomicAdd(&g_cur[s], 1);
    g_pos[e] = p;
    g_dstp[p] = __ldg(edst + e);
    float4 y = __ldg((const float4*)eattr + e);
    *((float4*)g_yp + p) = y;
}

// ======================================================================
// Fused edge MLP on tensor cores (tf32 mma.sync, fp32 accumulate).
//   128-edge tile, 8 warps; warp owns 16 edge rows of smem X [e][68].
//   phase1: h = silu(X @ W1/8) -> written in place over own rows
//   phase2: wf = h @ W2/8 -> g_wf at CSR slot pos[e]
//   Weights staged n-major [n][68], pre-scaled, tf32-rounded.
//   A/B fragment LDS are bank-conflict-free (bank = 4g + tIG).
// ======================================================================
__global__ void __launch_bounds__(256, 3) fused_mlp_kernel(
    const float* __restrict__ dist,
    const float* __restrict__ W1, const float* __restrict__ W2, int E)
{
    extern __shared__ float sm[];
    float* sX   = sm;                 // [128][68] = 8704 floats
    float* sW1T = sm + 8704;          // [64][68]  = 4352
    float* sW2T = sm + 13056;         // [80][68]  = 5440
    int t = threadIdx.x;

    // stage weights: transpose to n-major, scale 1/8, tf32-round
    for (int i = t; i < 4096; i += 256) {
        int k = i >> 6, n = i & 63;
        sW1T[n * 68 + k] = tf32r(__ldg(W1 + i) * 0.125f);
    }
    for (int i = t; i < 5120; i += 256) {
        int k = i / 80, n = i - k * 80;
        sW2T[n * 68 + k] = tf32r(__ldg(W2 + i) * 0.125f);
    }

    int e0 = blockIdx.x * TILE_E;

    // stage X rows (coalesced), tf32-round
    for (int i = t; i < TILE_E * 16; i += 256) {
        int e = i >> 4, seg = i & 15;
        float4 v = make_float4(0.f, 0.f, 0.f, 0.f);
        if (e0 + e < E)
            v = __ldg((const float4*)(dist + (size_t)(e0 + e) * 64) + seg);
        v.x = tf32r(v.x); v.y = tf32r(v.y); v.z = tf32r(v.z); v.w = tf32r(v.w);
        *(float4*)(sX + e * 68 + seg * 4) = v;
    }
    __syncthreads();

    int w = t >> 5, lane = t & 31;
    int g = lane >> 2, tIG = lane & 3;
    int r0 = 16 * w + g, r1 = r0 + 8;
    const float* x0 = sX + r0 * 68 + tIG;
    const float* x1 = sX + r1 * 68 + tIG;

    // A fragments for all 8 K-chunks (32 regs)
    float a[32];
#pragma unroll
    for (int c = 0; c < 8; c++) {
        a[4*c + 0] = x0[c * 8];
        a[4*c + 1] = x1[c * 8];
        a[4*c + 2] = x0[c * 8 + 4];
        a[4*c + 3] = x1[c * 8 + 4];
    }

    // ---------------- phase 1: h = silu(X @ W1/8), in place ----------------
#pragma unroll
    for (int nt = 0; nt < 8; nt++) {
        float c0 = 0.f, c1 = 0.f, c2 = 0.f, c3 = 0.f;
        const float* bp = sW1T + (nt * 8 + g) * 68 + tIG;
#pragma unroll
        for (int c = 0; c < 8; c++)
            mma_tf32(c0, c1, c2, c3,
                     a[4*c], a[4*c+1], a[4*c+2], a[4*c+3],
                     bp[c * 8], bp[c * 8 + 4]);
        // own rows only — safe (A fragments already in regs)
        *(float2*)(sX + r0 * 68 + nt * 8 + 2 * tIG) =
            make_float2(tf32r(silu(c0)), tf32r(silu(c1)));
        *(float2*)(sX + r1 * 68 + nt * 8 + 2 * tIG) =
            make_float2(tf32r(silu(c2)), tf32r(silu(c3)));
    }
    __syncwarp();   // cross-lane smem visibility within the warp

    // reload A fragments from h (same addresses)
#pragma unroll
    for (int c = 0; c < 8; c++) {
        a[4*c + 0] = x0[c * 8];
        a[4*c + 1] = x1[c * 8];
        a[4*c + 2] = x0[c * 8 + 4];
        a[4*c + 3] = x1[c * 8 + 4];
    }

    bool okLo = (e0 + r0) < E, okHi = (e0 + r1) < E;
    int posLo = okLo ? __ldg(g_pos + e0 + r0) : 0;
    int posHi = okHi ? __ldg(g_pos + e0 + r1) : 0;
    float* wLo = g_wf + (size_t)posLo * 80 + 2 * tIG;
    float* wHi = g_wf + (size_t)posHi * 80 + 2 * tIG;

    // ---------------- phase 2: wf = h @ W2/8 ----------------
#pragma unroll
    for (int nt = 0; nt < 10; nt++) {
        float c0 = 0.f, c1 = 0.f, c2 = 0.f, c3 = 0.f;
        const float* bp = sW2T + (nt * 8 + g) * 68 + tIG;
#pragma unroll
        for (int c = 0; c < 8; c++)
            mma_tf32(c0, c1, c2, c3,
                     a[4*c], a[4*c+1], a[4*c+2], a[4*c+3],
                     bp[c * 8], bp[c * 8 + 4]);
        if (okLo) *(float2*)(wLo + nt * 8) = make_float2(c0, c1);
        if (okHi) *(float2*)(wHi + nt * 8) = make_float2(c2, c3);
    }
}

// ======================================================================
// Kernel: self-interaction s = FCTP(x, attr; W_si)
// ======================================================================
__global__ void __launch_bounds__(128) node_pre_kernel(
    const float* __restrict__ xin, const float* __restrict__ attr,
    const float* __restrict__ Wsi0, const float* __restrict__ Wsi1, int N)
{
    __shared__ float w0[256], w1[256];
    int t = threadIdx.x;
    if (t < 128) { w0[t] = Wsi0[t]; w0[t + 128] = Wsi0[t + 128];
                   w1[t] = Wsi1[t]; w1[t + 128] = Wsi1[t + 128]; }
    __syncthreads();
    int n = blockIdx.x * 128 + t;
    if (n >= N) return;

    float x[64];
    const float4* xp = (const float4*)(xin + (size_t)n * 64);
#pragma unroll
    for (int qq = 0; qq < 16; qq++) {
        float4 v = __ldg(xp + qq);
        x[4*qq] = v.x; x[4*qq+1] = v.y; x[4*qq+2] = v.z; x[4*qq+3] = v.w;
    }
    float a = __ldg(attr + n) * 0.25f;  // attr / sqrt(16)

    float out[64];
#pragma unroll
    for (int u = 0; u < 16; u++) {
        float acc = 0.f;
#pragma unroll
        for (int v = 0; v < 16; v++) acc += x[v] * w0[u*16 + v];
        out[u] = acc * a;
    }
#pragma unroll
    for (int u = 0; u < 16; u++) {
        float a0 = 0.f, a1 = 0.f, a2 = 0.f;
#pragma unroll
        for (int v = 0; v < 16; v++) {
            float wv = w1[u*16 + v];
            a0 += x[16 + 3*v + 0] * wv;
            a1 += x[16 + 3*v + 1] * wv;
            a2 += x[16 + 3*v + 2] * wv;
        }
        out[16 + 3*u + 0] = a0 * a;
        out[16 + 3*u + 1] = a1 * a;
        out[16 + 3*u + 2] = a2 * a;
    }
    float4* sp = (float4*)(g_s + (size_t)n * 64);
#pragma unroll
    for (int qq = 0; qq < 16; qq++)
        sp[qq] = make_float4(out[4*qq], out[4*qq+1], out[4*qq+2], out[4*qq+3]);
}

// ======================================================================
// Aggregation: half-warp (16 lanes) per node, fully sequential CSR walk
// ======================================================================
__global__ void __launch_bounds__(256) agg_kernel(int N)
{
    int u = threadIdx.x & 15;
    int node = blockIdx.x * 16 + (threadIdx.x >> 4);

    int beg = 0, end = 0;
    if (node < N) { beg = __ldg(&g_off[node]); end = __ldg(&g_off[node + 1]); }

    const float is3 = 0.57735026918962576f;   // 1/sqrt(3)
    const float is2 = 0.70710678118654752f;   // 1/sqrt(2)

    float m0a = 0.f, m0b = 0.f;
    float A0 = 0.f, A1 = 0.f, A2 = 0.f;
    float B0 = 0.f, B1 = 0.f, B2 = 0.f;
    float C0 = 0.f, C1 = 0.f, C2 = 0.f;

#pragma unroll 2
    for (int p = beg; p < end; p++) {
        const float* wfp = g_wf + (size_t)p * 80;
        float w0 = __ldg(wfp + u);
        float w1 = __ldg(wfp + 16 + u);
        float w2 = __ldg(wfp + 32 + u);
        float w3 = __ldg(wfp + 48 + u);
        float w4 = __ldg(wfp + 64 + u) * is2;
        int dst = __ldg(g_dstp + p);
        float4 y = __ldg((const float4*)g_yp + p);
        const float* gs = g_s + (size_t)dst * 64;
        float g0 = __ldg(gs + u);
        float ga = __ldg(gs + 16 + 3*u);
        float gb = __ldg(gs + 17 + 3*u);
        float gc = __ldg(gs + 18 + 3*u);

        m0a += w0 * g0 * y.x;
        m0b += w3 * (ga*y.y + gb*y.z + gc*y.w) * is3;
        float w1g = w1 * g0;
        A0 += w1g * y.y;  A1 += w1g * y.z;  A2 += w1g * y.w;
        float w2y = w2 * y.x;
        B0 += w2y * ga;   B1 += w2y * gb;   B2 += w2y * gc;
        C0 += w4 * (gb * y.w - gc * y.z);
        C1 += w4 * (gc * y.y - ga * y.w);
        C2 += w4 * (ga * y.z - gb * y.y);
    }

    if (node < N) {
        float* ab = g_agg + (size_t)node * 176;
        ab[u]         = m0a;
        ab[16 + u]    = m0b;
        ab[32 + 3*u]  = A0;  ab[33 + 3*u]  = A1;  ab[34 + 3*u]  = A2;
        ab[80 + 3*u]  = B0;  ab[81 + 3*u]  = B1;  ab[82 + 3*u]  = B2;
        ab[128 + 3*u] = C0;  ab[129 + 3*u] = C1;  ab[130 + 3*u] = C2;
    }
}

// ======================================================================
// Kernel: per-node output + re-zero g_deg for the next graph replay
// ======================================================================
__global__ void __launch_bounds__(128) node_post_kernel(
    const float* __restrict__ xin, const float* __restrict__ attr,
    const float* __restrict__ Wsc0, const float* __restrict__ Wsc1,
    const float* __restrict__ Wlo0, const float* __restrict__ Wlo1,
    const float* __restrict__ Wal, float* __restrict__ out, int N)
{
    __shared__ float sc0[256], sc1[256], lo0[512], lo1[768], al[32];
    int t = threadIdx.x;
    for (int i = t; i < 256; i += 128) { sc0[i] = Wsc0[i]; sc1[i] = Wsc1[i]; }
    for (int i = t; i < 512; i += 128) lo0[i] = Wlo0[i];
    for (int i = t; i < 768; i += 128) lo1[i] = Wlo1[i];
    if (t < 32) al[t] = Wal[t];
    __syncthreads();

    int n = blockIdx.x * 128 + t;
    if (n >= N) return;

    g_deg[n] = 0;   // invariant for next replay

    const float* ag = g_agg + (size_t)n * 176;
    float o0[16], o1[48];
#pragma unroll
    for (int u = 0; u < 16; u++) o0[u] = 0.f;
#pragma unroll
    for (int j = 0; j < 48; j++) o1[j] = 0.f;
    float alpha = 0.f;

#pragma unroll
    for (int vg = 0; vg < 16; vg += 4) {
        float4 P = __ldg((const float4*)(ag + vg));
        float4 Q = __ldg((const float4*)(ag + 16 + vg));
        const float4* Ap = (const float4*)(ag + 32  + 3*vg);
        const float4* Bp = (const float4*)(ag + 80  + 3*vg);
        const float4* Cp = (const float4*)(ag + 128 + 3*vg);
        float4 Af0 = __ldg(Ap), Af1 = __ldg(Ap+1), Af2 = __ldg(Ap+2);
        float4 Bf0 = __ldg(Bp), Bf1 = __ldg(Bp+1), Bf2 = __ldg(Bp+2);
        float4 Cf0 = __ldg(Cp), Cf1 = __ldg(Cp+1), Cf2 = __ldg(Cp+2);
        float m0aq[4] = {P.x, P.y, P.z, P.w};
        float m0bq[4] = {Q.x, Q.y, Q.z, Q.w};
        float Aq[12] = {Af0.x,Af0.y,Af0.z,Af0.w,Af1.x,Af1.y,Af1.z,Af1.w,Af2.x,Af2.y,Af2.z,Af2.w};
        float Bq[12] = {Bf0.x,Bf0.y,Bf0.z,Bf0.w,Bf1.x,Bf1.y,Bf1.z,Bf1.w,Bf2.x,Bf2.y,Bf2.z,Bf2.w};
        float Cq[12] = {Cf0.x,Cf0.y,Cf0.z,Cf0.w,Cf1.x,Cf1.y,Cf1.z,Cf1.w,Cf2.x,Cf2.y,Cf2.z,Cf2.w};
#pragma unroll
        for (int j = 0; j < 4; j++) {
            int v = vg + j;
            float m0a = m0aq[j] * 0.25f;   // / sqrt(NUM_NEIGHBORS)
            float m0b = m0bq[j] * 0.25f;
            float Ax = Aq[3*j]*0.25f, Ay = Aq[3*j+1]*0.25f, Az = Aq[3*j+2]*0.25f;
            float Bx = Bq[3*j]*0.25f, By = Bq[3*j+1]*0.25f, Bz = Bq[3*j+2]*0.25f;
            float Cx = Cq[3*j]*0.25f, Cy = Cq[3*j+1]*0.25f, Cz = Cq[3*j+2]*0.25f;
            alpha += m0a * al[v] + m0b * al[16 + v];
#pragma unroll
            for (int u = 0; u < 16; u++) {
                o0[u] += m0a * lo0[u*32 + v] + m0b * lo0[u*32 + 16 + v];
                float wa = lo1[u*48 + v], wb = lo1[u*48 + 16 + v], wc = lo1[u*48 + 32 + v];
                o1[u*3 + 0] += Ax * wa + Bx * wb + Cx * wc;
                o1[u*3 + 1] += Ay * wa + By * wb + Cy * wc;
                o1[u*3 + 2] += Az * wa + Bz * wb + Cz * wc;
            }
        }
    }

    float x[64];
    const float4* xp = (const float4*)(xin + (size_t)n * 64);
#pragma unroll
    for (int qq = 0; qq < 16; qq++) {
        float4 v4 = __ldg(xp + qq);
        x[4*qq] = v4.x; x[4*qq+1] = v4.y; x[4*qq+2] = v4.z; x[4*qq+3] = v4.w;
    }
    float a   = __ldg(attr + n);
    float a4  = a * 0.25f;
    float s32 = a * 0.17677669529663689f;
    float s48 = a * 0.14433756729740643f;
    float alphaf = alpha * s32;

    float res[64];
#pragma unroll
    for (int u = 0; u < 16; u++) {
        float sk = 0.f;
#pragma unroll
        for (int v = 0; v < 16; v++) sk += x[v] * sc0[u*16 + v];
        res[u] = o0[u] * s32 * alphaf + sk * a4;
    }
#pragma unroll
    for (int u = 0; u < 16; u++) {
        float sa = 0.f, sb = 0.f, sc = 0.f;
#pragma unroll
        for (int v = 0; v < 16; v++) {
            float wv = sc1[u*16 + v];
            sa += x[16 + 3*v + 0] * wv;
            sb += x[16 + 3*v + 1] * wv;
            sc += x[16 + 3*v + 2] * wv;
        }
        res[16 + 3*u + 0] = o1[3*u + 0] * s48 * alphaf + sa * a4;
        res[16 + 3*u + 1] = o1[3*u + 1] * s48 * alphaf + sb * a4;
        res[16 + 3*u + 2] = o1[3*u + 2] * s48 * alphaf + sc * a4;
    }
    float4* op = (float4*)(out + (size_t)n * 64);
#pragma unroll
    for (int qq = 0; qq < 16; qq++)
        op[qq] = make_float4(res[4*qq], res[4*qq+1], res[4*qq+2], res[4*qq+3]);
}

// ======================================================================
extern "C" void kernel_launch(void* const* d_in, const int* in_sizes, int n_in,
                              void* d_out, int out_size)
{
    const float* node_input = (const float*)d_in[0];
    const float* node_attr  = (const float*)d_in[1];
    const int*   esrc       = (const int*)d_in[2];
    const int*   edst       = (const int*)d_in[3];
    const float* eattr      = (const float*)d_in[4];
    const float* dist       = (const float*)d_in[5];
    const float* Wsi0 = (const float*)d_in[6];
    const float* Wsi1 = (const float*)d_in[7];
    const float* Wsc0 = (const float*)d_in[8];
    const float* Wsc1 = (const float*)d_in[9];
    const float* Wm1  = (const float*)d_in[10];
    const float* Wm2  = (const float*)d_in[11];
    const float* Wlo0 = (const float*)d_in[12];
    const float* Wlo1 = (const float*)d_in[13];
    const float* Wal  = (const float*)d_in[14];

    int N = in_sizes[0] / 64;
    int E = in_sizes[2];

    int smem_bytes = (8704 + 4352 + 5440) * (int)sizeof(float);  // 73984
    cudaFuncSetAttribute(fused_mlp_kernel, cudaFuncAttributeMaxDynamicSharedMemorySize, smem_bytes);

    hist_kernel<<<(E + 255) / 256, 256>>>(esrc, E);                                   // 0
    scan_kernel<<<1, 1024>>>(N, E);                                                   // 1
    scatter_kernel<<<(E + 255) / 256, 256>>>(esrc, edst, eattr, E);                   // 2
    fused_mlp_kernel<<<(E + TILE_E - 1) / TILE_E, 256, smem_bytes>>>(dist, Wm1, Wm2, E); // 3 (profiled)
    node_pre_kernel<<<(N + 127) / 128, 128>>>(node_input, node_attr, Wsi0, Wsi1, N);  // 4
    agg_kernel<<<(N + 15) / 16, 256>>>(N);                                            // 5
    node_post_kernel<<<(N + 127) / 128, 128>>>(node_input, node_attr, Wsc0, Wsc1,
                                               Wlo0, Wlo1, Wal, (float*)d_out, N);    // 6
}

// round 10
// speedup vs baseline: 1.3611x; 1.0963x over previous
#include <cuda_runtime.h>
#include <cstdint>
#include <cstddef>

#define MAX_N 50000
#define MAX_E 800000
#define TILE_E 128

// Scratch (static device globals — no runtime allocation; zero-initialized)
__device__ float g_s[MAX_N * 64];            // per-node s0(16) + s1(16x3)
__device__ float g_agg[MAX_N * 176];         // m0a16|m0b16|m1a48|m1b48|m1c48
__device__ float g_wf[(size_t)MAX_E * 80];   // per-edge MLP out, CSR-permuted rows
__device__ float g_yp[(size_t)MAX_E * 4];    // eattr, CSR-permuted
__device__ int   g_dstp[MAX_E];              // edge dst, CSR-permuted
__device__ int   g_pos[MAX_E];               // edge -> CSR slot
__device__ int   g_deg[MAX_N];               // zeroed at end of each call
__device__ int   g_off[MAX_N + 1];
__device__ int   g_cur[MAX_N];

__device__ __forceinline__ float silu(float v) {
    return v / (1.f + __expf(-v));
}
// round f32 -> tf32 (rna), result held in an f32 register
__device__ __forceinline__ float tf32r(float x) {
    unsigned u;
    asm("cvt.rna.tf32.f32 %0, %1;" : "=r"(u) : "f"(x));
    return __uint_as_float(u);
}
// m16n8k8 tf32 MMA, accumulate in place
__device__ __forceinline__ void mma_tf32(
    float& d0, float& d1, float& d2, float& d3,
    float a0, float a1, float a2, float a3, float b0, float b1)
{
    asm volatile(
        "mma.sync.aligned.m16n8k8.row.col.f32.tf32.tf32.f32 "
        "{%0,%1,%2,%3}, {%4,%5,%6,%7}, {%8,%9}, {%0,%1,%2,%3};"
        : "+f"(d0), "+f"(d1), "+f"(d2), "+f"(d3)
        : "r"(__float_as_uint(a0)), "r"(__float_as_uint(a1)),
          "r"(__float_as_uint(a2)), "r"(__float_as_uint(a3)),
          "r"(__float_as_uint(b0)), "r"(__float_as_uint(b1)));
}

// ======================================================================
// CSR build
// ======================================================================
__global__ void __launch_bounds__(256) hist_kernel(const int* __restrict__ esrc, int E)
{
    int e = blockIdx.x * 256 + threadIdx.x;
    if (e < E) atomicAdd(&g_deg[__ldg(esrc + e)], 1);
}

__global__ void __launch_bounds__(1024) scan_kernel(int N, int E)
{
    __shared__ int part[1024];
    int t = threadIdx.x;
    const int chunk = (MAX_N + 1023) / 1024;   // 49
    int start = t * chunk;
    int end = start + chunk; if (end > N) end = N;
    int s = 0;
    if (start < N) for (int i = start; i < end; i++) s += g_deg[i];
    part[t] = s;
    __syncthreads();
    for (int off = 1; off < 1024; off <<= 1) {
        int v = (t >= off) ? part[t - off] : 0;
        __syncthreads();
        part[t] += v;
        __syncthreads();
    }
    int run = part[t] - s;
    if (start < N) {
        for (int i = start; i < end; i++) {
            g_off[i] = run;
            g_cur[i] = run;
            run += g_deg[i];
        }
    }
    if (t == 0) g_off[N] = E;
}

__global__ void __launch_bounds__(256) scatter_kernel(
    const int* __restrict__ esrc, const int* __restrict__ edst,
    const float* __restrict__ eattr, int E)
{
    int e = blockIdx.x * 256 + threadIdx.x;
    if (e >= E) return;
    int s = __ldg(esrc + e);
    int p = atomicAdd(&g_cur[s], 1);
    g_pos[e] = p;
    g_dstp[p] = __ldg(edst + e);
    float4 y = __ldg((const float4*)eattr + e);
    *((float4*)g_yp + p) = y;
}

// ======================================================================
// Fused edge MLP on tensor cores (tf32 mma.sync, fp32 accumulate).
//   128-edge tile, 8 warps; warp owns 16 edge rows of smem X [e][68].
//   Weights staged in FRAGMENT order: sWF[((nt*8+c)*32+lane)*2 + {0,1}]
//   = B[k=c*8+tIG (+4)][n=nt*8+g]  -> one conflict-free LDS.64 per mma.
// ======================================================================
__global__ void __launch_bounds__(256, 3) fused_mlp_kernel(
    const float* __restrict__ dist,
    const float* __restrict__ W1, const float* __restrict__ W2, int E)
{
    extern __shared__ float sm[];
    float* sX   = sm;                 // [128][68] = 8704 floats
    float* sW1F = sm + 8704;          // 4096 floats, fragment order
    float* sW2F = sm + 12800;         // 5120 floats, fragment order
    int t = threadIdx.x;

    // stage weights in fragment order, scale 1/8, tf32-round
    for (int i = t; i < 2048; i += 256) {          // W1: 8 nt x 8 c x 32 lanes
        int nt = i >> 8, rem = i & 255;
        int c = rem >> 5, ln = rem & 31;
        int gg = ln >> 2, tg = ln & 3;
        int n = nt * 8 + gg, k0 = c * 8 + tg;
        sW1F[2*i]     = tf32r(__ldg(W1 + k0 * 64 + n) * 0.125f);
        sW1F[2*i + 1] = tf32r(__ldg(W1 + (k0 + 4) * 64 + n) * 0.125f);
    }
    for (int i = t; i < 2560; i += 256) {          // W2: 10 nt x 8 c x 32 lanes
        int nt = i >> 8, rem = i & 255;
        int c = rem >> 5, ln = rem & 31;
        int gg = ln >> 2, tg = ln & 3;
        int n = nt * 8 + gg, k0 = c * 8 + tg;
        sW2F[2*i]     = tf32r(__ldg(W2 + k0 * 80 + n) * 0.125f);
        sW2F[2*i + 1] = tf32r(__ldg(W2 + (k0 + 4) * 80 + n) * 0.125f);
    }

    int e0 = blockIdx.x * TILE_E;

    // stage X rows (coalesced), tf32-round
    for (int i = t; i < TILE_E * 16; i += 256) {
        int e = i >> 4, seg = i & 15;
        float4 v = make_float4(0.f, 0.f, 0.f, 0.f);
        if (e0 + e < E)
            v = __ldg((const float4*)(dist + (size_t)(e0 + e) * 64) + seg);
        v.x = tf32r(v.x); v.y = tf32r(v.y); v.z = tf32r(v.z); v.w = tf32r(v.w);
        *(float4*)(sX + e * 68 + seg * 4) = v;
    }
    __syncthreads();

    int w = t >> 5, lane = t & 31;
    int g = lane >> 2, tIG = lane & 3;
    int r0 = 16 * w + g, r1 = r0 + 8;
    const float* x0 = sX + r0 * 68 + tIG;
    const float* x1 = sX + r1 * 68 + tIG;

    // A fragments for all 8 K-chunks (32 regs)
    float a[32];
#pragma unroll
    for (int c = 0; c < 8; c++) {
        a[4*c + 0] = x0[c * 8];
        a[4*c + 1] = x1[c * 8];
        a[4*c + 2] = x0[c * 8 + 4];
        a[4*c + 3] = x1[c * 8 + 4];
    }

    // ---------------- phase 1: h = silu(X @ W1/8), in place ----------------
    {
        const float2* bf = (const float2*)sW1F + lane;
#pragma unroll
        for (int nt = 0; nt < 8; nt++) {
            float c0 = 0.f, c1 = 0.f, c2 = 0.f, c3 = 0.f;
#pragma unroll
            for (int c = 0; c < 8; c++) {
                float2 b = bf[(nt * 8 + c) * 32];
                mma_tf32(c0, c1, c2, c3,
                         a[4*c], a[4*c+1], a[4*c+2], a[4*c+3], b.x, b.y);
            }
            *(float2*)(sX + r0 * 68 + nt * 8 + 2 * tIG) =
                make_float2(tf32r(silu(c0)), tf32r(silu(c1)));
            *(float2*)(sX + r1 * 68 + nt * 8 + 2 * tIG) =
                make_float2(tf32r(silu(c2)), tf32r(silu(c3)));
        }
    }
    __syncwarp();   // cross-lane smem visibility within the warp

    // reload A fragments from h (same addresses)
#pragma unroll
    for (int c = 0; c < 8; c++) {
        a[4*c + 0] = x0[c * 8];
        a[4*c + 1] = x1[c * 8];
        a[4*c + 2] = x0[c * 8 + 4];
        a[4*c + 3] = x1[c * 8 + 4];
    }

    bool okLo = (e0 + r0) < E, okHi = (e0 + r1) < E;
    int posLo = okLo ? __ldg(g_pos + e0 + r0) : 0;
    int posHi = okHi ? __ldg(g_pos + e0 + r1) : 0;
    float* wLo = g_wf + (size_t)posLo * 80 + 2 * tIG;
    float* wHi = g_wf + (size_t)posHi * 80 + 2 * tIG;

    // ---------------- phase 2: wf = h @ W2/8 ----------------
    {
        const float2* bf = (const float2*)sW2F + lane;
#pragma unroll
        for (int nt = 0; nt < 10; nt++) {
            float c0 = 0.f, c1 = 0.f, c2 = 0.f, c3 = 0.f;
#pragma unroll
            for (int c = 0; c < 8; c++) {
                float2 b = bf[(nt * 8 + c) * 32];
                mma_tf32(c0, c1, c2, c3,
                         a[4*c], a[4*c+1], a[4*c+2], a[4*c+3], b.x, b.y);
            }
            if (okLo) *(float2*)(wLo + nt * 8) = make_float2(c0, c1);
            if (okHi) *(float2*)(wHi + nt * 8) = make_float2(c2, c3);
        }
    }
}

// ======================================================================
// Kernel: self-interaction s = FCTP(x, attr; W_si)
// ======================================================================
__global__ void __launch_bounds__(128) node_pre_kernel(
    const float* __restrict__ xin, const float* __restrict__ attr,
    const float* __restrict__ Wsi0, const float* __restrict__ Wsi1, int N)
{
    __shared__ float w0[256], w1[256];
    int t = threadIdx.x;
    if (t < 128) { w0[t] = Wsi0[t]; w0[t + 128] = Wsi0[t + 128];
                   w1[t] = Wsi1[t]; w1[t + 128] = Wsi1[t + 128]; }
    __syncthreads();
    int n = blockIdx.x * 128 + t;
    if (n >= N) return;

    float x[64];
    const float4* xp = (const float4*)(xin + (size_t)n * 64);
#pragma unroll
    for (int qq = 0; qq < 16; qq++) {
        float4 v = __ldg(xp + qq);
        x[4*qq] = v.x; x[4*qq+1] = v.y; x[4*qq+2] = v.z; x[4*qq+3] = v.w;
    }
    float a = __ldg(attr + n) * 0.25f;  // attr / sqrt(16)

    float out[64];
#pragma unroll
    for (int u = 0; u < 16; u++) {
        float acc = 0.f;
#pragma unroll
        for (int v = 0; v < 16; v++) acc += x[v] * w0[u*16 + v];
        out[u] = acc * a;
    }
#pragma unroll
    for (int u = 0; u < 16; u++) {
        float a0 = 0.f, a1 = 0.f, a2 = 0.f;
#pragma unroll
        for (int v = 0; v < 16; v++) {
            float wv = w1[u*16 + v];
            a0 += x[16 + 3*v + 0] * wv;
            a1 += x[16 + 3*v + 1] * wv;
            a2 += x[16 + 3*v + 2] * wv;
        }
        out[16 + 3*u + 0] = a0 * a;
        out[16 + 3*u + 1] = a1 * a;
        out[16 + 3*u + 2] = a2 * a;
    }
    float4* sp = (float4*)(g_s + (size_t)n * 64);
#pragma unroll
    for (int qq = 0; qq < 16; qq++)
        sp[qq] = make_float4(out[4*qq], out[4*qq+1], out[4*qq+2], out[4*qq+3]);
}

// ======================================================================
// Aggregation: full warp per node, TWO edges in flight
//   (lanes 0-15 = channels of edge p, lanes 16-31 = channels of edge p+1),
//   final cross-half merge via shfl.xor 16. No atomics.
// ======================================================================
__global__ void __launch_bounds__(256) agg_kernel(int N)
{
    int lane = threadIdx.x & 31;
    int u    = lane & 15;
    int par  = lane >> 4;
    int node = blockIdx.x * 8 + (threadIdx.x >> 5);

    int beg = 0, end = 0;
    if (node < N) { beg = __ldg(&g_off[node]); end = __ldg(&g_off[node + 1]); }

    const float is3 = 0.57735026918962576f;   // 1/sqrt(3)
    const float is2 = 0.70710678118654752f;   // 1/sqrt(2)

    float m0a = 0.f, m0b = 0.f;
    float A0 = 0.f, A1 = 0.f, A2 = 0.f;
    float B0 = 0.f, B1 = 0.f, B2 = 0.f;
    float C0 = 0.f, C1 = 0.f, C2 = 0.f;

    for (int p = beg + par; p < end; p += 2) {
        const float* wfp = g_wf + (size_t)p * 80;
        float w0 = __ldg(wfp + u);
        float w1 = __ldg(wfp + 16 + u);
        float w2 = __ldg(wfp + 32 + u);
        float w3 = __ldg(wfp + 48 + u);
        float w4 = __ldg(wfp + 64 + u) * is2;
        int dst = __ldg(g_dstp + p);
        float4 y = __ldg((const float4*)g_yp + p);
        const float* gs = g_s + (size_t)dst * 64;
        float g0 = __ldg(gs + u);
        float ga = __ldg(gs + 16 + 3*u);
        float gb = __ldg(gs + 17 + 3*u);
        float gc = __ldg(gs + 18 + 3*u);

        m0a += w0 * g0 * y.x;
        m0b += w3 * (ga*y.y + gb*y.z + gc*y.w) * is3;
        float w1g = w1 * g0;
        A0 += w1g * y.y;  A1 += w1g * y.z;  A2 += w1g * y.w;
        float w2y = w2 * y.x;
        B0 += w2y * ga;   B1 += w2y * gb;   B2 += w2y * gc;
        C0 += w4 * (gb * y.w - gc * y.z);
        C1 += w4 * (gc * y.y - ga * y.w);
        C2 += w4 * (ga * y.z - gb * y.y);
    }

    // merge the two halves (same u, opposite parity)
    m0a += __shfl_xor_sync(0xffffffffu, m0a, 16);
    m0b += __shfl_xor_sync(0xffffffffu, m0b, 16);
    A0  += __shfl_xor_sync(0xffffffffu, A0, 16);
    A1  += __shfl_xor_sync(0xffffffffu, A1, 16);
    A2  += __shfl_xor_sync(0xffffffffu, A2, 16);
    B0  += __shfl_xor_sync(0xffffffffu, B0, 16);
    B1  += __shfl_xor_sync(0xffffffffu, B1, 16);
    B2  += __shfl_xor_sync(0xffffffffu, B2, 16);
    C0  += __shfl_xor_sync(0xffffffffu, C0, 16);
    C1  += __shfl_xor_sync(0xffffffffu, C1, 16);
    C2  += __shfl_xor_sync(0xffffffffu, C2, 16);

    if (node < N && par == 0) {
        float* ab = g_agg + (size_t)node * 176;
        ab[u]         = m0a;
        ab[16 + u]    = m0b;
        ab[32 + 3*u]  = A0;  ab[33 + 3*u]  = A1;  ab[34 + 3*u]  = A2;
        ab[80 + 3*u]  = B0;  ab[81 + 3*u]  = B1;  ab[82 + 3*u]  = B2;
        ab[128 + 3*u] = C0;  ab[129 + 3*u] = C1;  ab[130 + 3*u] = C2;
    }
}

// ======================================================================
// Kernel: per-node output + re-zero g_deg for the next graph replay
// ======================================================================
__global__ void __launch_bounds__(128) node_post_kernel(
    const float* __restrict__ xin, const float* __restrict__ attr,
    const float* __restrict__ Wsc0, const float* __restrict__ Wsc1,
    const float* __restrict__ Wlo0, const float* __restrict__ Wlo1,
    const float* __restrict__ Wal, float* __restrict__ out, int N)
{
    __shared__ float sc0[256], sc1[256], lo0[512], lo1[768], al[32];
    int t = threadIdx.x;
    for (int i = t; i < 256; i += 128) { sc0[i] = Wsc0[i]; sc1[i] = Wsc1[i]; }
    for (int i = t; i < 512; i += 128) lo0[i] = Wlo0[i];
    for (int i = t; i < 768; i += 128) lo1[i] = Wlo1[i];
    if (t < 32) al[t] = Wal[t];
    __syncthreads();

    int n = blockIdx.x * 128 + t;
    if (n >= N) return;

    g_deg[n] = 0;   // invariant for next replay

    const float* ag = g_agg + (size_t)n * 176;
    float o0[16], o1[48];
#pragma unroll
    for (int u = 0; u < 16; u++) o0[u] = 0.f;
#pragma unroll
    for (int j = 0; j < 48; j++) o1[j] = 0.f;
    float alpha = 0.f;

#pragma unroll
    for (int vg = 0; vg < 16; vg += 4) {
        float4 P = __ldg((const float4*)(ag + vg));
        float4 Q = __ldg((const float4*)(ag + 16 + vg));
        const float4* Ap = (const float4*)(ag + 32  + 3*vg);
        const float4* Bp = (const float4*)(ag + 80  + 3*vg);
        const float4* Cp = (const float4*)(ag + 128 + 3*vg);
        float4 Af0 = __ldg(Ap), Af1 = __ldg(Ap+1), Af2 = __ldg(Ap+2);
        float4 Bf0 = __ldg(Bp), Bf1 = __ldg(Bp+1), Bf2 = __ldg(Bp+2);
        float4 Cf0 = __ldg(Cp), Cf1 = __ldg(Cp+1), Cf2 = __ldg(Cp+2);
        float m0aq[4] = {P.x, P.y, P.z, P.w};
        float m0bq[4] = {Q.x, Q.y, Q.z, Q.w};
        float Aq[12] = {Af0.x,Af0.y,Af0.z,Af0.w,Af1.x,Af1.y,Af1.z,Af1.w,Af2.x,Af2.y,Af2.z,Af2.w};
        float Bq[12] = {Bf0.x,Bf0.y,Bf0.z,Bf0.w,Bf1.x,Bf1.y,Bf1.z,Bf1.w,Bf2.x,Bf2.y,Bf2.z,Bf2.w};
        float Cq[12] = {Cf0.x,Cf0.y,Cf0.z,Cf0.w,Cf1.x,Cf1.y,Cf1.z,Cf1.w,Cf2.x,Cf2.y,Cf2.z,Cf2.w};
#pragma unroll
        for (int j = 0; j < 4; j++) {
            int v = vg + j;
            float m0a = m0aq[j] * 0.25f;   // / sqrt(NUM_NEIGHBORS)
            float m0b = m0bq[j] * 0.25f;
            float Ax = Aq[3*j]*0.25f, Ay = Aq[3*j+1]*0.25f, Az = Aq[3*j+2]*0.25f;
            float Bx = Bq[3*j]*0.25f, By = Bq[3*j+1]*0.25f, Bz = Bq[3*j+2]*0.25f;
            float Cx = Cq[3*j]*0.25f, Cy = Cq[3*j+1]*0.25f, Cz = Cq[3*j+2]*0.25f;
            alpha += m0a * al[v] + m0b * al[16 + v];
#pragma unroll
            for (int u = 0; u < 16; u++) {
                o0[u] += m0a * lo0[u*32 + v] + m0b * lo0[u*32 + 16 + v];
                float wa = lo1[u*48 + v], wb = lo1[u*48 + 16 + v], wc = lo1[u*48 + 32 + v];
                o1[u*3 + 0] += Ax * wa + Bx * wb + Cx * wc;
                o1[u*3 + 1] += Ay * wa + By * wb + Cy * wc;
                o1[u*3 + 2] += Az * wa + Bz * wb + Cz * wc;
            }
        }
    }

    float x[64];
    const float4* xp = (const float4*)(xin + (size_t)n * 64);
#pragma unroll
    for (int qq = 0; qq < 16; qq++) {
        float4 v4 = __ldg(xp + qq);
        x[4*qq] = v4.x; x[4*qq+1] = v4.y; x[4*qq+2] = v4.z; x[4*qq+3] = v4.w;
    }
    float a   = __ldg(attr + n);
    float a4  = a * 0.25f;
    float s32 = a * 0.17677669529663689f;
    float s48 = a * 0.14433756729740643f;
    float alphaf = alpha * s32;

    float res[64];
#pragma unroll
    for (int u = 0; u < 16; u++) {
        float sk = 0.f;
#pragma unroll
        for (int v = 0; v < 16; v++) sk += x[v] * sc0[u*16 + v];
        res[u] = o0[u] * s32 * alphaf + sk * a4;
    }
#pragma unroll
    for (int u = 0; u < 16; u++) {
        float sa = 0.f, sb = 0.f, sc = 0.f;
#pragma unroll
        for (int v = 0; v < 16; v++) {
            float wv = sc1[u*16 + v];
            sa += x[16 + 3*v + 0] * wv;
            sb += x[16 + 3*v + 1] * wv;
            sc += x[16 + 3*v + 2] * wv;
        }
        res[16 + 3*u + 0] = o1[3*u + 0] * s48 * alphaf + sa * a4;
        res[16 + 3*u + 1] = o1[3*u + 1] * s48 * alphaf + sb * a4;
        res[16 + 3*u + 2] = o1[3*u + 2] * s48 * alphaf + sc * a4;
    }
    float4* op = (float4*)(out + (size_t)n * 64);
#pragma unroll
    for (int qq = 0; qq < 16; qq++)
        op[qq] = make_float4(res[4*qq], res[4*qq+1], res[4*qq+2], res[4*qq+3]);
}

// ======================================================================
extern "C" void kernel_launch(void* const* d_in, const int* in_sizes, int n_in,
                              void* d_out, int out_size)
{
    const float* node_input = (const float*)d_in[0];
    const float* node_attr  = (const float*)d_in[1];
    const int*   esrc       = (const int*)d_in[2];
    const int*   edst       = (const int*)d_in[3];
    const float* eattr      = (const float*)d_in[4];
    const float* dist       = (const float*)d_in[5];
    const float* Wsi0 = (const float*)d_in[6];
    const float* Wsi1 = (const float*)d_in[7];
    const float* Wsc0 = (const float*)d_in[8];
    const float* Wsc1 = (const float*)d_in[9];
    const float* Wm1  = (const float*)d_in[10];
    const float* Wm2  = (const float*)d_in[11];
    const float* Wlo0 = (const float*)d_in[12];
    const float* Wlo1 = (const float*)d_in[13];
    const float* Wal  = (const float*)d_in[14];

    int N = in_sizes[0] / 64;
    int E = in_sizes[2];

    int smem_bytes = (8704 + 4096 + 5120) * (int)sizeof(float);  // 71680
    cudaFuncSetAttribute(fused_mlp_kernel, cudaFuncAttributeMaxDynamicSharedMemorySize, smem_bytes);

    hist_kernel<<<(E + 255) / 256, 256>>>(esrc, E);                                   // 0
    scan_kernel<<<1, 1024>>>(N, E);                                                   // 1
    scatter_kernel<<<(E + 255) / 256, 256>>>(esrc, edst, eattr, E);                   // 2
    fused_mlp_kernel<<<(E + TILE_E - 1) / TILE_E, 256, smem_bytes>>>(dist, Wm1, Wm2, E); // 3 (profiled)
    node_pre_kernel<<<(N + 127) / 128, 128>>>(node_input, node_attr, Wsi0, Wsi1, N);  // 4
    agg_kernel<<<(N + 7) / 8, 256>>>(N);                                              // 5
    node_post_kernel<<<(N + 127) / 128, 128>>>(node_input, node_attr, Wsc0, Wsc1,
                                               Wlo0, Wlo1, Wal, (float*)d_out, N);    // 6
}